// round 15
// baseline (speedup 1.0000x reference)
#include <cuda_runtime.h>
#include <cuda_fp16.h>
#include <cstdint>

#define N_NODES 50000
#define MAX_E   800000
#define DIM_IN  128
#define DIM_HID 256
#define DIM_OUT 128

#define SCAN_B  256
#define NPART   ((N_NODES + SCAN_B - 1) / SCAN_B)   // 196

// ---------------- scratch (static __device__, allocation-free) ----------------
__device__ int    g_is64;
__device__ int    g_base;
__device__ int    g_cnt[N_NODES];
__device__ int    g_row[N_NODES];
__device__ int    g_cursor[N_NODES];
__device__ int2   g_csr[MAX_E];                     // packed {src, w_bits}
__device__ int2   g_sd[MAX_E];                      // staged {src, dst}
__device__ float  g_dinv[N_NODES];
__device__ __half g_xh[(size_t)N_NODES * 128];      // x in half
__device__ __half g_b128h[(size_t)N_NODES * 128];   // agg1 in half
__device__ __half g_a1h[(size_t)N_NODES * 256];     // relu acts in half
__device__ __half g_th[(size_t)N_NODES * 128];      // t = a1@W2 in half
__device__ __half g_w1t[DIM_HID * DIM_IN];          // W1^T in half [256][128]
__device__ __half g_w2t[DIM_OUT * DIM_HID];         // W2^T in half [128][256]

// ---------------- helpers ----------------
__device__ __forceinline__ int edge_idx(const void* __restrict__ ei, long long pos) {
    if (g_is64) return (int)((const long long*)ei)[pos];
    return ((const int*)ei)[pos];
}

__device__ __forceinline__ uint32_t smem_u32(const void* p) {
    return (uint32_t)__cvta_generic_to_shared(p);
}
__device__ __forceinline__ void cp16(uint32_t dst, const void* src, bool pred) {
    int sz = pred ? 16 : 0;
    asm volatile("cp.async.ca.shared.global [%0], [%1], 16, %2;"
                 :: "r"(dst), "l"(src), "r"(sz));
}
__device__ __forceinline__ void ldsm_x4(uint32_t& r0, uint32_t& r1,
                                        uint32_t& r2, uint32_t& r3, uint32_t addr) {
    asm volatile("ldmatrix.sync.aligned.m8n8.x4.shared.b16 {%0,%1,%2,%3}, [%4];"
                 : "=r"(r0), "=r"(r1), "=r"(r2), "=r"(r3) : "r"(addr));
}

// ------- init: zero counters, sniff dtype, W1/W2 -> half transposed -----------
__global__ void k_init(const int* __restrict__ ei, const float* __restrict__ W1,
                       const float* __restrict__ W2) {
    int i = blockIdx.x * blockDim.x + threadIdx.x;     // 65536 threads
    if (i < N_NODES) g_cnt[i] = 0;
    if (i < DIM_IN * DIM_HID) {                        // W1T[n][k] = W1[k][n]
        int n = i >> 7, k = i & 127;
        g_w1t[i] = __float2half(W1[k * DIM_HID + n]);
    }
    if (i < DIM_HID * DIM_OUT) {                       // W2T[n][k] = W2[k][n]
        int n = i >> 8, k = i & 255;
        g_w2t[i] = __float2half(W2[k * DIM_OUT + n]);
    }
    if (i == 0) {
        g_base = 0;
        int is64 = 1;
        for (int k = 1; k < 64; k += 2)
            if (ei[k] != 0) { is64 = 0; break; }
        g_is64 = is64;
    }
}

// ------- hist + int2 staging + x->half conversion (fused) ---------------------
__global__ void k_hist_f2h(const void* __restrict__ ei, const float* __restrict__ x,
                           int E) {
    int i = blockIdx.x * blockDim.x + threadIdx.x;
    if (i < E) {
        int s = edge_idx(ei, i);
        int d = edge_idx(ei, (long long)E + i);
        g_sd[i] = make_int2(s, d);
        if ((unsigned)s < N_NODES && (unsigned)d < N_NODES)
            atomicAdd(&g_cnt[d], 1);
    }
    if (i < N_NODES * 32) {
        float4 v = ((const float4*)x)[i];
        __half2 h0 = __floats2half2_rn(v.x, v.y);
        __half2 h1 = __floats2half2_rn(v.z, v.w);
        uint2 o;
        o.x = *(uint32_t*)&h0;
        o.y = *(uint32_t*)&h1;
        ((uint2*)g_xh)[i] = o;
    }
}

// ---------------- single-kernel scan+fill (atomic block base) -----------------
__global__ void k_scanfill() {
    int b = blockIdx.x, t = threadIdx.x;
    int i = b * SCAN_B + t;
    int c = (i < N_NODES) ? g_cnt[i] : 0;
    int lane = t & 31, wid = t >> 5;
    int v = c;
    #pragma unroll
    for (int o = 1; o < 32; o <<= 1) {
        int u = __shfl_up_sync(0xffffffff, v, o);
        if (lane >= o) v += u;
    }
    __shared__ int ws[8];
    __shared__ int sbase;
    if (lane == 31) ws[wid] = v;
    __syncthreads();
    if (wid == 0 && lane < 8) {
        int w = ws[lane];
        #pragma unroll
        for (int o = 1; o < 8; o <<= 1) {
            int u = __shfl_up_sync(0xff, w, o);
            if (lane >= o) w += u;
        }
        ws[lane] = w;
    }
    __syncthreads();
    if (t == 0) sbase = atomicAdd(&g_base, ws[7]);
    __syncthreads();
    int excl = v - c + (wid > 0 ? ws[wid - 1] : 0) + sbase;
    if (i < N_NODES) {
        g_row[i] = excl;
        g_cursor[i] = excl;
        g_dinv[i] = rsqrtf((float)(c + 1));   // +1 self-loop
    }
}

// ------- scatter: 4 edges/thread, batched loads -> overlapping chains ---------
__global__ void k_scatter(int E) {
    int i = blockIdx.x * blockDim.x + threadIdx.x;
    int base = i * 4;
    int2 sd[4];
    bool ok[4];
    #pragma unroll
    for (int u = 0; u < 4; u++) {
        int e = base + u;
        ok[u] = e < E;
        if (ok[u]) sd[u] = __ldg(&g_sd[e]);
    }
    #pragma unroll
    for (int u = 0; u < 4; u++)
        ok[u] = ok[u] && (unsigned)sd[u].x < N_NODES && (unsigned)sd[u].y < N_NODES;
    float ws[4], wd[4];
    #pragma unroll
    for (int u = 0; u < 4; u++) {
        ws[u] = ok[u] ? __ldg(&g_dinv[sd[u].x]) : 0.f;
        wd[u] = ok[u] ? __ldg(&g_dinv[sd[u].y]) : 0.f;
    }
    #pragma unroll
    for (int u = 0; u < 4; u++) {
        if (ok[u]) {
            int pos = atomicAdd(&g_cursor[sd[u].y], 1);
            g_csr[pos] = make_int2(sd[u].x, __float_as_int(ws[u] * wd[u]));
        }
    }
}

// ------- pull aggregation (half feats, fp32 acc, exact unroll 8/4/1) ----------
// HALF_OUT: emit half (feeds fp16 GEMM A); else fp32 with bias.
template <bool BIAS, bool HALF_OUT>
__global__ void k_agg_h(const __half* __restrict__ feat, float* __restrict__ out,
                        __half* __restrict__ outh, const float* __restrict__ bias) {
    int t = blockIdx.x * blockDim.x + threadIdx.x;
    int d = t >> 5;
    if (d >= N_NODES) return;
    int lane = t & 31;

    const uint2* f2 = (const uint2*)feat;
    float dd = g_dinv[d];
    float sl = dd * dd;

    uint2 sv = __ldg(&f2[(size_t)d * 32 + lane]);
    float2 a0 = __half22float2(*(__half2*)&sv.x);
    float2 a1 = __half22float2(*(__half2*)&sv.y);
    float4 acc;
    acc.x = a0.x * sl; acc.y = a0.y * sl; acc.z = a1.x * sl; acc.w = a1.y * sl;

    int beg = g_row[d];
    int end = beg + g_cnt[d];
    int j = beg;
    // exact 8-batches: 8 gathers in flight, no wasted traffic
    for (; j + 8 <= end; j += 8) {
        int2  e[8];
        uint2 v[8];
        #pragma unroll
        for (int u = 0; u < 8; u++) e[u] = __ldg(&g_csr[j + u]);
        #pragma unroll
        for (int u = 0; u < 8; u++) v[u] = __ldg(&f2[(size_t)e[u].x * 32 + lane]);
        #pragma unroll
        for (int u = 0; u < 8; u++) {
            float w = __int_as_float(e[u].y);
            float2 x0 = __half22float2(*(__half2*)&v[u].x);
            float2 x1 = __half22float2(*(__half2*)&v[u].y);
            acc.x = fmaf(x0.x, w, acc.x); acc.y = fmaf(x0.y, w, acc.y);
            acc.z = fmaf(x1.x, w, acc.z); acc.w = fmaf(x1.y, w, acc.w);
        }
    }
    for (; j + 4 <= end; j += 4) {
        int2  e[4];
        uint2 v[4];
        #pragma unroll
        for (int u = 0; u < 4; u++) e[u] = __ldg(&g_csr[j + u]);
        #pragma unroll
        for (int u = 0; u < 4; u++) v[u] = __ldg(&f2[(size_t)e[u].x * 32 + lane]);
        #pragma unroll
        for (int u = 0; u < 4; u++) {
            float w = __int_as_float(e[u].y);
            float2 x0 = __half22float2(*(__half2*)&v[u].x);
            float2 x1 = __half22float2(*(__half2*)&v[u].y);
            acc.x = fmaf(x0.x, w, acc.x); acc.y = fmaf(x0.y, w, acc.y);
            acc.z = fmaf(x1.x, w, acc.z); acc.w = fmaf(x1.y, w, acc.w);
        }
    }
    for (; j < end; j++) {
        int2 e = __ldg(&g_csr[j]);
        float w = __int_as_float(e.y);
        uint2 v = __ldg(&f2[(size_t)e.x * 32 + lane]);
        float2 x0 = __half22float2(*(__half2*)&v.x);
        float2 x1 = __half22float2(*(__half2*)&v.y);
        acc.x = fmaf(x0.x, w, acc.x); acc.y = fmaf(x0.y, w, acc.y);
        acc.z = fmaf(x1.x, w, acc.z); acc.w = fmaf(x1.y, w, acc.w);
    }
    if (BIAS) {
        float4 b = ((const float4*)bias)[lane];
        acc.x += b.x; acc.y += b.y; acc.z += b.z; acc.w += b.w;
    }
    if (HALF_OUT) {
        __half2 h0 = __floats2half2_rn(acc.x, acc.y);
        __half2 h1 = __floats2half2_rn(acc.z, acc.w);
        uint2 o;
        o.x = *(uint32_t*)&h0;
        o.y = *(uint32_t*)&h1;
        ((uint2*)outh)[(size_t)d * 32 + lane] = o;
    } else {
        ((float4*)out)[(size_t)d * 32 + lane] = acc;
    }
}

// ---------------- fp16 tensor-core GEMM (cp.async + ldmatrix) -----------------
// C = A[M,K] @ B[K,N] (+bias) (+relu), A half row-major, BT half [N][K].
// BM=128, BN=64, BK=32, 2 stages, 8 warps (4m x 2n), warp tile 32x32.
__device__ __forceinline__ void mma_f16(float c[4], const uint32_t a[4],
                                        const uint32_t b[2]) {
    asm volatile(
        "mma.sync.aligned.m16n8k16.row.col.f32.f16.f16.f32 "
        "{%0,%1,%2,%3}, {%4,%5,%6,%7}, {%8,%9}, {%0,%1,%2,%3};"
        : "+f"(c[0]), "+f"(c[1]), "+f"(c[2]), "+f"(c[3])
        : "r"(a[0]), "r"(a[1]), "r"(a[2]), "r"(a[3]), "r"(b[0]), "r"(b[1]));
}

template <bool RELU, bool BIAS>
__global__ void __launch_bounds__(256)
k_gemm_h(const __half* __restrict__ A, const __half* __restrict__ BT,
         const float* __restrict__ bias, __half* __restrict__ C,
         int M, int K, int N) {
    __shared__ __half As[2][128][40];   // [m][k] pad 40
    __shared__ __half Bs[2][64][40];    // [n][k] pad 40

    int tid  = threadIdx.x;
    int lane = tid & 31, wid = tid >> 5;
    int wm = wid & 3, wn = wid >> 2;          // 4 x 2 warps
    int gid = lane >> 2, ctg = lane & 3;
    int bm = blockIdx.y * 128, bn = blockIdx.x * 64;

    int lrow = lane & 15;
    int lcol = (lane >> 4) * 8;

    const int NT = K / 32;

    auto issue_tile = [&](int kt, int stage) {
        int k0 = kt * 32;
        #pragma unroll
        for (int i = 0; i < 2; i++) {
            int c = tid + i * 256;            // 0..511
            int r = c >> 2, off = (c & 3) * 8;
            bool ok = (bm + r) < M;
            cp16(smem_u32(&As[stage][r][off]),
                 A + (size_t)(bm + r) * K + k0 + off, ok);
        }
        {
            int r = tid >> 2, off = (tid & 3) * 8;
            cp16(smem_u32(&Bs[stage][r][off]),
                 BT + (size_t)(bn + r) * K + k0 + off, true);
        }
        asm volatile("cp.async.commit_group;");
    };

    float acc[2][4][4] = {};

    issue_tile(0, 0);
    for (int kt = 0; kt < NT; kt++) {
        int cur = kt & 1;
        if (kt + 1 < NT) {
            issue_tile(kt + 1, cur ^ 1);
            asm volatile("cp.async.wait_group 1;");
        } else {
            asm volatile("cp.async.wait_group 0;");
        }
        __syncthreads();

        #pragma unroll
        for (int ks = 0; ks < 2; ks++) {      // two k16 steps per k32 tile
            int kk = ks * 16;
            uint32_t a[2][4], b[4][2];
            #pragma unroll
            for (int mi = 0; mi < 2; mi++) {
                int m0 = wm * 32 + mi * 16;
                ldsm_x4(a[mi][0], a[mi][1], a[mi][2], a[mi][3],
                        smem_u32(&As[cur][m0 + lrow][kk + lcol]));
            }
            #pragma unroll
            for (int nip = 0; nip < 2; nip++) {
                int n0 = wn * 32 + nip * 16;
                ldsm_x4(b[2 * nip][0], b[2 * nip + 1][0],
                        b[2 * nip][1], b[2 * nip + 1][1],
                        smem_u32(&Bs[cur][n0 + lrow][kk + lcol]));
            }
            #pragma unroll
            for (int mi = 0; mi < 2; mi++)
                #pragma unroll
                for (int ni = 0; ni < 4; ni++)
                    mma_f16(acc[mi][ni], a[mi], b[ni]);
        }
        __syncthreads();
    }

    #pragma unroll
    for (int mi = 0; mi < 2; mi++) {
        #pragma unroll
        for (int ni = 0; ni < 4; ni++) {
            int r0 = bm + wm * 32 + mi * 16 + gid;
            int c  = bn + wn * 32 + ni * 8 + ctg * 2;
            float2 v0 = make_float2(acc[mi][ni][0], acc[mi][ni][1]);
            float2 v1 = make_float2(acc[mi][ni][2], acc[mi][ni][3]);
            if (BIAS) {
                float2 bb = *(const float2*)&bias[c];
                v0.x += bb.x; v0.y += bb.y;
                v1.x += bb.x; v1.y += bb.y;
            }
            if (RELU) {
                v0.x = fmaxf(v0.x, 0.f); v0.y = fmaxf(v0.y, 0.f);
                v1.x = fmaxf(v1.x, 0.f); v1.y = fmaxf(v1.y, 0.f);
            }
            __half2 h0 = __floats2half2_rn(v0.x, v0.y);
            __half2 h1 = __floats2half2_rn(v1.x, v1.y);
            if (r0 < M)     *(__half2*)(C + (size_t)r0 * N + c) = h0;
            if (r0 + 8 < M) *(__half2*)(C + (size_t)(r0 + 8) * N + c) = h1;
        }
    }
}

// ---------------- launch ----------------
extern "C" void kernel_launch(void* const* d_in, const int* in_sizes, int n_in,
                              void* d_out, int out_size) {
    const float* x  = (const float*)d_in[0];
    const void*  ei = d_in[1];
    const float* W1 = (const float*)d_in[2];
    const float* b1 = (const float*)d_in[3];
    const float* W2 = (const float*)d_in[4];
    const float* b2 = (const float*)d_in[5];
    float*       out = (float*)d_out;

    const int E = in_sizes[1] / 2;

    __half *xh = nullptr, *b128h = nullptr, *a1h = nullptr, *th = nullptr;
    __half *w1t = nullptr, *w2t = nullptr;
    cudaGetSymbolAddress((void**)&xh, g_xh);
    cudaGetSymbolAddress((void**)&b128h, g_b128h);
    cudaGetSymbolAddress((void**)&a1h, g_a1h);
    cudaGetSymbolAddress((void**)&th, g_th);
    cudaGetSymbolAddress((void**)&w1t, g_w1t);
    cudaGetSymbolAddress((void**)&w2t, g_w2t);

    const int fuse_items = N_NODES * 32;   // 1.6M >= E
    k_init<<<256, 256>>>((const int*)ei, W1, W2);          // 65536 threads
    k_hist_f2h<<<(fuse_items + 255) / 256, 256>>>(ei, x, E);
    k_scanfill<<<NPART, SCAN_B>>>();
    k_scatter<<<((E + 3) / 4 + 255) / 256, 256>>>(E);

    const int agg_blocks = (N_NODES * 32 + 255) / 256;

    // ---- layer 1: agg1 = S x (half out) ; a1 = relu(agg1 @ W1 + b1) (half) ----
    k_agg_h<false, true><<<agg_blocks, 256>>>(xh, nullptr, b128h, nullptr);
    {
        dim3 grid(DIM_HID / 64, (N_NODES + 127) / 128);
        k_gemm_h<true, true><<<grid, 256>>>(b128h, w1t, b1, a1h,
                                            N_NODES, DIM_IN, DIM_HID);
    }

    // ---- layer 2: t = a1 @ W2 (half out) ; out = S t + b2 ----
    {
        dim3 grid(DIM_OUT / 64, (N_NODES + 127) / 128);
        k_gemm_h<false, false><<<grid, 256>>>(a1h, w2t, nullptr, th,
                                              N_NODES, DIM_HID, DIM_OUT);
    }
    k_agg_h<true, false><<<agg_blocks, 256>>>(th, out, nullptr, b2);
}

// round 16
// speedup vs baseline: 1.0976x; 1.0976x over previous
#include <cuda_runtime.h>
#include <cuda_fp16.h>
#include <cstdint>

#define N_NODES 50000
#define MAX_E   800000
#define DIM_IN  128
#define DIM_HID 256
#define DIM_OUT 128

#define SCAN_B  256
#define NPART   ((N_NODES + SCAN_B - 1) / SCAN_B)   // 196

// ---------------- scratch (static __device__, allocation-free) ----------------
__device__ int      g_is64;
__device__ int      g_base;
__device__ int      g_cnt[N_NODES];
__device__ int      g_row[N_NODES];
__device__ int      g_cursor[N_NODES];
__device__ uint32_t g_csr4[MAX_E];                  // packed src<<16 | half(w)
__device__ int2     g_sd[MAX_E];                    // staged {src, dst}
__device__ float    g_dinv[N_NODES];
__device__ __half   g_xh[(size_t)N_NODES * 128];    // x in half
__device__ __half   g_b128h[(size_t)N_NODES * 128]; // agg1 in half
__device__ __half   g_a1h[(size_t)N_NODES * 256];   // relu acts in half
__device__ __half   g_th[(size_t)N_NODES * 128];    // t = a1@W2 in half
__device__ __half   g_w1t[DIM_HID * DIM_IN];        // W1^T in half [256][128]
__device__ __half   g_w2t[DIM_OUT * DIM_HID];       // W2^T in half [128][256]

// ---------------- helpers ----------------
__device__ __forceinline__ int edge_idx(const void* __restrict__ ei, long long pos) {
    if (g_is64) return (int)((const long long*)ei)[pos];
    return ((const int*)ei)[pos];
}

__device__ __forceinline__ uint32_t smem_u32(const void* p) {
    return (uint32_t)__cvta_generic_to_shared(p);
}
__device__ __forceinline__ void cp16(uint32_t dst, const void* src, bool pred) {
    int sz = pred ? 16 : 0;
    asm volatile("cp.async.ca.shared.global [%0], [%1], 16, %2;"
                 :: "r"(dst), "l"(src), "r"(sz));
}
__device__ __forceinline__ void ldsm_x4(uint32_t& r0, uint32_t& r1,
                                        uint32_t& r2, uint32_t& r3, uint32_t addr) {
    asm volatile("ldmatrix.sync.aligned.m8n8.x4.shared.b16 {%0,%1,%2,%3}, [%4];"
                 : "=r"(r0), "=r"(r1), "=r"(r2), "=r"(r3) : "r"(addr));
}

// ------- init: zero counters, sniff dtype, W1/W2 -> half transposed -----------
__global__ void k_init(const int* __restrict__ ei, const float* __restrict__ W1,
                       const float* __restrict__ W2) {
    int i = blockIdx.x * blockDim.x + threadIdx.x;     // 65536 threads
    if (i < N_NODES) g_cnt[i] = 0;
    if (i < DIM_IN * DIM_HID) {                        // W1T[n][k] = W1[k][n]
        int n = i >> 7, k = i & 127;
        g_w1t[i] = __float2half(W1[k * DIM_HID + n]);
    }
    if (i < DIM_HID * DIM_OUT) {                       // W2T[n][k] = W2[k][n]
        int n = i >> 8, k = i & 255;
        g_w2t[i] = __float2half(W2[k * DIM_OUT + n]);
    }
    if (i == 0) {
        g_base = 0;
        int is64 = 1;
        for (int k = 1; k < 64; k += 2)
            if (ei[k] != 0) { is64 = 0; break; }
        g_is64 = is64;
    }
}

// ------- hist + int2 staging + x->half conversion (fused) ---------------------
__global__ void k_hist_f2h(const void* __restrict__ ei, const float* __restrict__ x,
                           int E) {
    int i = blockIdx.x * blockDim.x + threadIdx.x;
    if (i < E) {
        int s = edge_idx(ei, i);
        int d = edge_idx(ei, (long long)E + i);
        g_sd[i] = make_int2(s, d);
        if ((unsigned)s < N_NODES && (unsigned)d < N_NODES)
            atomicAdd(&g_cnt[d], 1);
    }
    if (i < N_NODES * 32) {
        float4 v = ((const float4*)x)[i];
        __half2 h0 = __floats2half2_rn(v.x, v.y);
        __half2 h1 = __floats2half2_rn(v.z, v.w);
        uint2 o;
        o.x = *(uint32_t*)&h0;
        o.y = *(uint32_t*)&h1;
        ((uint2*)g_xh)[i] = o;
    }
}

// ---------------- single-kernel scan+fill (atomic block base) -----------------
__global__ void k_scanfill() {
    int b = blockIdx.x, t = threadIdx.x;
    int i = b * SCAN_B + t;
    int c = (i < N_NODES) ? g_cnt[i] : 0;
    int lane = t & 31, wid = t >> 5;
    int v = c;
    #pragma unroll
    for (int o = 1; o < 32; o <<= 1) {
        int u = __shfl_up_sync(0xffffffff, v, o);
        if (lane >= o) v += u;
    }
    __shared__ int ws[8];
    __shared__ int sbase;
    if (lane == 31) ws[wid] = v;
    __syncthreads();
    if (wid == 0 && lane < 8) {
        int w = ws[lane];
        #pragma unroll
        for (int o = 1; o < 8; o <<= 1) {
            int u = __shfl_up_sync(0xff, w, o);
            if (lane >= o) w += u;
        }
        ws[lane] = w;
    }
    __syncthreads();
    if (t == 0) sbase = atomicAdd(&g_base, ws[7]);
    __syncthreads();
    int excl = v - c + (wid > 0 ? ws[wid - 1] : 0) + sbase;
    if (i < N_NODES) {
        g_row[i] = excl;
        g_cursor[i] = excl;
        g_dinv[i] = rsqrtf((float)(c + 1));   // +1 self-loop
    }
}

// ------- scatter: 1 edge/thread, 4-byte packed {src16, w_fp16} ----------------
__global__ void k_scatter(int E) {
    int e = blockIdx.x * blockDim.x + threadIdx.x;
    if (e >= E) return;
    int2 sd = __ldg(&g_sd[e]);
    if ((unsigned)sd.y >= N_NODES || (unsigned)sd.x >= N_NODES) return;
    float w = g_dinv[sd.x] * g_dinv[sd.y];
    uint32_t packed = ((uint32_t)sd.x << 16) |
                      (uint32_t)__half_as_ushort(__float2half_rn(w));
    int pos = atomicAdd(&g_cursor[sd.y], 1);
    g_csr4[pos] = packed;
}

// ------- pull aggregation (half feats, fp32 acc, unroll x4, 4B CSR) -----------
// HALF_OUT: emit half (feeds fp16 GEMM A); else fp32 with bias.
template <bool BIAS, bool HALF_OUT>
__global__ void k_agg_h(const __half* __restrict__ feat, float* __restrict__ out,
                        __half* __restrict__ outh, const float* __restrict__ bias) {
    int t = blockIdx.x * blockDim.x + threadIdx.x;
    int d = t >> 5;
    if (d >= N_NODES) return;
    int lane = t & 31;

    const uint2* f2 = (const uint2*)feat;
    float dd = g_dinv[d];
    float sl = dd * dd;

    uint2 sv = __ldg(&f2[(size_t)d * 32 + lane]);
    float2 a0 = __half22float2(*(__half2*)&sv.x);
    float2 a1 = __half22float2(*(__half2*)&sv.y);
    float4 acc;
    acc.x = a0.x * sl; acc.y = a0.y * sl; acc.z = a1.x * sl; acc.w = a1.y * sl;

    int beg = g_row[d];
    int end = beg + g_cnt[d];
    int j = beg;
    for (; j + 4 <= end; j += 4) {
        uint32_t e0 = __ldg(&g_csr4[j + 0]);
        uint32_t e1 = __ldg(&g_csr4[j + 1]);
        uint32_t e2 = __ldg(&g_csr4[j + 2]);
        uint32_t e3 = __ldg(&g_csr4[j + 3]);
        uint2 v0 = __ldg(&f2[(size_t)(e0 >> 16) * 32 + lane]);
        uint2 v1 = __ldg(&f2[(size_t)(e1 >> 16) * 32 + lane]);
        uint2 v2 = __ldg(&f2[(size_t)(e2 >> 16) * 32 + lane]);
        uint2 v3 = __ldg(&f2[(size_t)(e3 >> 16) * 32 + lane]);
        float w0 = __half2float(__ushort_as_half((unsigned short)(e0 & 0xFFFF)));
        float w1 = __half2float(__ushort_as_half((unsigned short)(e1 & 0xFFFF)));
        float w2 = __half2float(__ushort_as_half((unsigned short)(e2 & 0xFFFF)));
        float w3 = __half2float(__ushort_as_half((unsigned short)(e3 & 0xFFFF)));
        {
            float2 x0 = __half22float2(*(__half2*)&v0.x);
            float2 x1 = __half22float2(*(__half2*)&v0.y);
            acc.x = fmaf(x0.x, w0, acc.x); acc.y = fmaf(x0.y, w0, acc.y);
            acc.z = fmaf(x1.x, w0, acc.z); acc.w = fmaf(x1.y, w0, acc.w);
        }
        {
            float2 x0 = __half22float2(*(__half2*)&v1.x);
            float2 x1 = __half22float2(*(__half2*)&v1.y);
            acc.x = fmaf(x0.x, w1, acc.x); acc.y = fmaf(x0.y, w1, acc.y);
            acc.z = fmaf(x1.x, w1, acc.z); acc.w = fmaf(x1.y, w1, acc.w);
        }
        {
            float2 x0 = __half22float2(*(__half2*)&v2.x);
            float2 x1 = __half22float2(*(__half2*)&v2.y);
            acc.x = fmaf(x0.x, w2, acc.x); acc.y = fmaf(x0.y, w2, acc.y);
            acc.z = fmaf(x1.x, w2, acc.z); acc.w = fmaf(x1.y, w2, acc.w);
        }
        {
            float2 x0 = __half22float2(*(__half2*)&v3.x);
            float2 x1 = __half22float2(*(__half2*)&v3.y);
            acc.x = fmaf(x0.x, w3, acc.x); acc.y = fmaf(x0.y, w3, acc.y);
            acc.z = fmaf(x1.x, w3, acc.z); acc.w = fmaf(x1.y, w3, acc.w);
        }
    }
    for (; j < end; j++) {
        uint32_t e = __ldg(&g_csr4[j]);
        float w = __half2float(__ushort_as_half((unsigned short)(e & 0xFFFF)));
        uint2 v = __ldg(&f2[(size_t)(e >> 16) * 32 + lane]);
        float2 x0 = __half22float2(*(__half2*)&v.x);
        float2 x1 = __half22float2(*(__half2*)&v.y);
        acc.x = fmaf(x0.x, w, acc.x); acc.y = fmaf(x0.y, w, acc.y);
        acc.z = fmaf(x1.x, w, acc.z); acc.w = fmaf(x1.y, w, acc.w);
    }
    if (BIAS) {
        float4 b = ((const float4*)bias)[lane];
        acc.x += b.x; acc.y += b.y; acc.z += b.z; acc.w += b.w;
    }
    if (HALF_OUT) {
        __half2 h0 = __floats2half2_rn(acc.x, acc.y);
        __half2 h1 = __floats2half2_rn(acc.z, acc.w);
        uint2 o;
        o.x = *(uint32_t*)&h0;
        o.y = *(uint32_t*)&h1;
        ((uint2*)outh)[(size_t)d * 32 + lane] = o;
    } else {
        ((float4*)out)[(size_t)d * 32 + lane] = acc;
    }
}

// ---------------- fp16 tensor-core GEMM (cp.async + ldmatrix) -----------------
// C = A[M,K] @ B[K,N] (+bias) (+relu), A half row-major, BT half [N][K].
// BM=128, BN=64, BK=32, 2 stages, 8 warps (4m x 2n), warp tile 32x32.
__device__ __forceinline__ void mma_f16(float c[4], const uint32_t a[4],
                                        const uint32_t b[2]) {
    asm volatile(
        "mma.sync.aligned.m16n8k16.row.col.f32.f16.f16.f32 "
        "{%0,%1,%2,%3}, {%4,%5,%6,%7}, {%8,%9}, {%0,%1,%2,%3};"
        : "+f"(c[0]), "+f"(c[1]), "+f"(c[2]), "+f"(c[3])
        : "r"(a[0]), "r"(a[1]), "r"(a[2]), "r"(a[3]), "r"(b[0]), "r"(b[1]));
}

template <bool RELU, bool BIAS>
__global__ void __launch_bounds__(256)
k_gemm_h(const __half* __restrict__ A, const __half* __restrict__ BT,
         const float* __restrict__ bias, __half* __restrict__ C,
         int M, int K, int N) {
    __shared__ __half As[2][128][40];   // [m][k] pad 40
    __shared__ __half Bs[2][64][40];    // [n][k] pad 40

    int tid  = threadIdx.x;
    int lane = tid & 31, wid = tid >> 5;
    int wm = wid & 3, wn = wid >> 2;          // 4 x 2 warps
    int gid = lane >> 2, ctg = lane & 3;
    int bm = blockIdx.y * 128, bn = blockIdx.x * 64;

    int lrow = lane & 15;
    int lcol = (lane >> 4) * 8;

    const int NT = K / 32;

    auto issue_tile = [&](int kt, int stage) {
        int k0 = kt * 32;
        #pragma unroll
        for (int i = 0; i < 2; i++) {
            int c = tid + i * 256;            // 0..511
            int r = c >> 2, off = (c & 3) * 8;
            bool ok = (bm + r) < M;
            cp16(smem_u32(&As[stage][r][off]),
                 A + (size_t)(bm + r) * K + k0 + off, ok);
        }
        {
            int r = tid >> 2, off = (tid & 3) * 8;
            cp16(smem_u32(&Bs[stage][r][off]),
                 BT + (size_t)(bn + r) * K + k0 + off, true);
        }
        asm volatile("cp.async.commit_group;");
    };

    float acc[2][4][4] = {};

    issue_tile(0, 0);
    for (int kt = 0; kt < NT; kt++) {
        int cur = kt & 1;
        if (kt + 1 < NT) {
            issue_tile(kt + 1, cur ^ 1);
            asm volatile("cp.async.wait_group 1;");
        } else {
            asm volatile("cp.async.wait_group 0;");
        }
        __syncthreads();

        #pragma unroll
        for (int ks = 0; ks < 2; ks++) {      // two k16 steps per k32 tile
            int kk = ks * 16;
            uint32_t a[2][4], b[4][2];
            #pragma unroll
            for (int mi = 0; mi < 2; mi++) {
                int m0 = wm * 32 + mi * 16;
                ldsm_x4(a[mi][0], a[mi][1], a[mi][2], a[mi][3],
                        smem_u32(&As[cur][m0 + lrow][kk + lcol]));
            }
            #pragma unroll
            for (int nip = 0; nip < 2; nip++) {
                int n0 = wn * 32 + nip * 16;
                ldsm_x4(b[2 * nip][0], b[2 * nip + 1][0],
                        b[2 * nip][1], b[2 * nip + 1][1],
                        smem_u32(&Bs[cur][n0 + lrow][kk + lcol]));
            }
            #pragma unroll
            for (int mi = 0; mi < 2; mi++)
                #pragma unroll
                for (int ni = 0; ni < 4; ni++)
                    mma_f16(acc[mi][ni], a[mi], b[ni]);
        }
        __syncthreads();
    }

    #pragma unroll
    for (int mi = 0; mi < 2; mi++) {
        #pragma unroll
        for (int ni = 0; ni < 4; ni++) {
            int r0 = bm + wm * 32 + mi * 16 + gid;
            int c  = bn + wn * 32 + ni * 8 + ctg * 2;
            float2 v0 = make_float2(acc[mi][ni][0], acc[mi][ni][1]);
            float2 v1 = make_float2(acc[mi][ni][2], acc[mi][ni][3]);
            if (BIAS) {
                float2 bb = *(const float2*)&bias[c];
                v0.x += bb.x; v0.y += bb.y;
                v1.x += bb.x; v1.y += bb.y;
            }
            if (RELU) {
                v0.x = fmaxf(v0.x, 0.f); v0.y = fmaxf(v0.y, 0.f);
                v1.x = fmaxf(v1.x, 0.f); v1.y = fmaxf(v1.y, 0.f);
            }
            __half2 h0 = __floats2half2_rn(v0.x, v0.y);
            __half2 h1 = __floats2half2_rn(v1.x, v1.y);
            if (r0 < M)     *(__half2*)(C + (size_t)r0 * N + c) = h0;
            if (r0 + 8 < M) *(__half2*)(C + (size_t)(r0 + 8) * N + c) = h1;
        }
    }
}

// ---------------- launch ----------------
extern "C" void kernel_launch(void* const* d_in, const int* in_sizes, int n_in,
                              void* d_out, int out_size) {
    const float* x  = (const float*)d_in[0];
    const void*  ei = d_in[1];
    const float* W1 = (const float*)d_in[2];
    const float* b1 = (const float*)d_in[3];
    const float* W2 = (const float*)d_in[4];
    const float* b2 = (const float*)d_in[5];
    float*       out = (float*)d_out;

    const int E = in_sizes[1] / 2;

    __half *xh = nullptr, *b128h = nullptr, *a1h = nullptr, *th = nullptr;
    __half *w1t = nullptr, *w2t = nullptr;
    cudaGetSymbolAddress((void**)&xh, g_xh);
    cudaGetSymbolAddress((void**)&b128h, g_b128h);
    cudaGetSymbolAddress((void**)&a1h, g_a1h);
    cudaGetSymbolAddress((void**)&th, g_th);
    cudaGetSymbolAddress((void**)&w1t, g_w1t);
    cudaGetSymbolAddress((void**)&w2t, g_w2t);

    const int fuse_items = N_NODES * 32;   // 1.6M >= E
    k_init<<<256, 256>>>((const int*)ei, W1, W2);          // 65536 threads
    k_hist_f2h<<<(fuse_items + 255) / 256, 256>>>(ei, x, E);
    k_scanfill<<<NPART, SCAN_B>>>();
    k_scatter<<<(E + 255) / 256, 256>>>(E);

    const int agg_blocks = (N_NODES * 32 + 255) / 256;

    // ---- layer 1: agg1 = S x (half out) ; a1 = relu(agg1 @ W1 + b1) (half) ----
    k_agg_h<false, true><<<agg_blocks, 256>>>(xh, nullptr, b128h, nullptr);
    {
        dim3 grid(DIM_HID / 64, (N_NODES + 127) / 128);
        k_gemm_h<true, true><<<grid, 256>>>(b128h, w1t, b1, a1h,
                                            N_NODES, DIM_IN, DIM_HID);
    }

    // ---- layer 2: t = a1 @ W2 (half out) ; out = S t + b2 ----
    {
        dim3 grid(DIM_OUT / 64, (N_NODES + 127) / 128);
        k_gemm_h<false, false><<<grid, 256>>>(a1h, w2t, nullptr, th,
                                              N_NODES, DIM_HID, DIM_OUT);
    }
    k_agg_h<true, false><<<agg_blocks, 256>>>(th, out, nullptr, b2);
}